// round 6
// baseline (speedup 1.0000x reference)
#include <cuda_runtime.h>
#include <math.h>

// R6 == R5 resubmission: round-5 bench died with an infra-level container
// failure before producing any result; barrier audited for deadlock (none).

#define E0    90112
#define F     16
#define N0    1408
#define GRID  128
#define BLOCK 512
#define NT    (GRID * BLOCK)
#define NSUB  8
#define SUBSZ (GRID / NSUB)     // 16 arrivals per sub-counter

// ---------------- persistent device state ----------------
__device__ unsigned int g_sub[NSUB * 64];  // sub-counters, 256B apart (distinct LTS slices)
__device__ unsigned int g_master;
__device__ unsigned int g_gen;             // monotonic generation
__device__ int          g_ecnt[4];         // compacted edge count per layer ([0] unused)
__device__ __align__(16) float g_h   [N0 * F];
__device__ __align__(16) float g_outA[N0 * F];      // conv accum, layers 0,2
__device__ __align__(16) float g_outB[704 * F];     // conv accum, layers 1,3
__device__ __align__(16) float g_xp3 [88 * F];      // final pooled features (FC input)
__device__ float g_deg [4][N0];            // edge-degree (self-loop added at use); self-cleaning
__device__ int   g_pos [N0];               // old -> new (or -1)
__device__ int   g_row [4][E0];
__device__ int   g_col [4][E0];
__device__ float g_h1[1024];
__device__ float g_h2[512];

// ---------------- two-level tree barrier ----------------
__device__ __forceinline__ void gsync() {
    __syncthreads();
    if (threadIdx.x == 0) {
        unsigned int gen;
        asm volatile("ld.acquire.gpu.u32 %0, [%1];" : "=r"(gen) : "l"(&g_gen) : "memory");
        unsigned int* sub = &g_sub[(blockIdx.x & (NSUB - 1)) * 64];
        unsigned int old;
        asm volatile("atom.add.acq_rel.gpu.u32 %0, [%1], 1;"
                     : "=r"(old) : "l"(sub) : "memory");
        bool released = false;
        if (old == SUBSZ - 1u) {           // last arrival in this subgroup
            asm volatile("st.relaxed.gpu.u32 [%0], 0;" :: "l"(sub) : "memory");
            unsigned int mold;
            asm volatile("atom.add.acq_rel.gpu.u32 %0, [%1], 1;"
                         : "=r"(mold) : "l"(&g_master) : "memory");
            if (mold == NSUB - 1u) {       // last subgroup -> release everyone
                asm volatile("st.relaxed.gpu.u32 [%0], 0;" :: "l"(&g_master) : "memory");
                asm volatile("st.release.gpu.u32 [%0], %1;"
                             :: "l"(&g_gen), "r"(gen + 1u) : "memory");
                released = true;
            }
        }
        if (!released) {
            unsigned int cur;
            do {
                asm volatile("ld.acquire.gpu.u32 %0, [%1];" : "=r"(cur) : "l"(&g_gen) : "memory");
            } while (cur == gen);
        }
    }
    __syncthreads();
}

__device__ __forceinline__ void red_add_v4(float* addr, float a, float b, float c, float d) {
    asm volatile("red.global.add.v4.f32 [%0], {%1, %2, %3, %4};"
                 :: "l"(addr), "f"(a), "f"(b), "f"(c), "f"(d) : "memory");
}

__global__ void __launch_bounds__(BLOCK, 1) gcn_fused(
    const float* __restrict__ x, const int* __restrict__ ei,
    const float* __restrict__ W0, const float* __restrict__ b0,
    const float* __restrict__ W1, const float* __restrict__ b1,
    const float* __restrict__ W2, const float* __restrict__ b2,
    const float* __restrict__ W3, const float* __restrict__ b3,
    const float* __restrict__ pw0, const float* __restrict__ pw1,
    const float* __restrict__ pw2, const float* __restrict__ pw3,
    const float* __restrict__ fw1, const float* __restrict__ fb1,
    const float* __restrict__ fw2, const float* __restrict__ fb2,
    const float* __restrict__ fw3, const float* __restrict__ fb3,
    float* __restrict__ out)
{
    const int gtid = blockIdx.x * BLOCK + threadIdx.x;
    const int lane = threadIdx.x & 31;
    __shared__ unsigned long long s_keys[N0];   // 11.3 KB, max layer size

    const int    ns[4]  = {1408, 704, 352, 176};
    const float* Ws[4]  = {W0, W1, W2, W3};
    const float* bs[4]  = {b0, b1, b2, b3};
    const float* pws[4] = {pw0, pw1, pw2, pw3};
    float* const obuf[4] = {g_outA, g_outB, g_outA, g_outB};

    // ---------- Phase M: init + edge copy + deg0 + gemm0 + zero outA + FC seeds ----------
    for (int idx = gtid; idx < E0; idx += NT) {
        int r = ei[idx], c = ei[E0 + idx];
        g_row[0][idx] = r;
        g_col[0][idx] = c;
        atomicAdd(&g_deg[0][c], 1.0f);
    }
    for (int idx = gtid; idx < N0 * F; idx += NT) {
        int i = idx >> 4, j = idx & 15;
        const float* xr = x + i * 128;
        float acc = 0.0f;
        #pragma unroll 16
        for (int k = 0; k < 128; k++) acc += xr[k] * W0[k * F + j];
        g_h[idx] = acc;
        g_outA[idx] = 0.0f;
    }
    if (gtid < 1024) g_h1[gtid] = fb1[gtid];
    if (gtid < 512)  g_h2[gtid] = fb2[gtid];
    if (gtid < 96)   out[gtid]  = fb3[gtid];
    if (gtid == 0) { g_ecnt[1] = 0; g_ecnt[2] = 0; g_ecnt[3] = 0; }
    gsync();

    // ---------- per layer: S (scatter) | P (rank-select+gather+gemm) | E (edge remap) ----------
    for (int l = 0; l < 4; l++) {
        const int n  = ns[l];
        const int K  = n >> 1;
        const int El = (l == 0) ? E0 : g_ecnt[l];
        float* outL  = obuf[l];
        const float* degL = g_deg[l];

        // Phase S: self-loop + edge scatter (norm from deg on the fly)
        for (int t = gtid; t < n + El; t += NT) {
            if (t < n) {
                float dv2 = 1.0f / (degL[t] + 1.0f);
                const float4* hr = (const float4*)&g_h[t * F];
                float* oc = &outL[t * F];
                #pragma unroll
                for (int q = 0; q < 4; q++) {
                    float4 hv = hr[q];
                    red_add_v4(oc + 4 * q, dv2 * hv.x, dv2 * hv.y, dv2 * hv.z, dv2 * hv.w);
                }
            } else {
                int e = t - n;
                int r = g_row[l][e], c = g_col[l][e];
                float norm = __frsqrt_rn(degL[r] + 1.0f) * __frsqrt_rn(degL[c] + 1.0f);
                const float4* hr = (const float4*)&g_h[r * F];
                float* oc = &outL[c * F];
                #pragma unroll
                for (int q = 0; q < 4; q++) {
                    float4 hv = hr[q];
                    red_add_v4(oc + 4 * q, norm * hv.x, norm * hv.y, norm * hv.z, norm * hv.w);
                }
            }
        }
        gsync();

        // Phase P: parallel rank-selection. Each active block recomputes all n keys into
        // its own smem; warp w ranks node i = global warp id. Fused gather+gemm on select.
        {
            for (int i = gtid; i < n; i += NT) g_deg[l][i] = 0.0f;   // self-clean for replay
            const float* pw = pws[l];
            const float* bb = bs[l];
            if (blockIdx.x * (BLOCK / 32) < n) {
                float npw = 0.0f;
                #pragma unroll
                for (int f = 0; f < F; f++) { float v = pw[f]; npw += v * v; }
                npw = sqrtf(npw);

                for (int i = threadIdx.x; i < n; i += BLOCK) {
                    float s = 0.0f;
                    #pragma unroll
                    for (int f = 0; f < F; f++) {
                        float v = outL[i * F + f] + bb[f];
                        v = v > 0.0f ? v : 0.0f;
                        s += v * pw[f];
                    }
                    float sc = tanhf(s / npw);
                    int bits = __float_as_int(sc);
                    unsigned int ka = (bits >= 0) ? (0x80000000u + (unsigned int)bits)
                                                  : ~(unsigned int)bits;
                    s_keys[i] = ((unsigned long long)(~ka) << 32) | (unsigned int)i;
                }
                __syncthreads();

                int i = blockIdx.x * (BLOCK / 32) + (threadIdx.x >> 5);
                if (i < n) {
                    unsigned long long ki = s_keys[i];
                    int cnt = 0;
                    for (int j = lane; j < n; j += 32) cnt += (s_keys[j] < ki) ? 1 : 0;
                    int rank = __reduce_add_sync(0xFFFFFFFFu, cnt);
                    if (rank < K) {
                        unsigned int ka = ~(unsigned int)(ki >> 32);
                        int bits = (ka >= 0x80000000u) ? (int)(ka - 0x80000000u) : (int)(~ka);
                        float val = __int_as_float(bits);
                        if (lane == 0) g_pos[i] = rank;
                        if (lane < F) {
                            if (l < 3) {
                                const float* Wn = Ws[l + 1];
                                float* outN = (l & 1) ? g_outA : g_outB;
                                float acc = 0.0f;
                                #pragma unroll
                                for (int f = 0; f < F; f++) {
                                    float v = outL[i * F + f] + bb[f];
                                    v = v > 0.0f ? v : 0.0f;
                                    acc += v * Wn[f * F + lane];
                                }
                                g_h[rank * F + lane] = acc * val;
                                outN[rank * F + lane] = 0.0f;
                            } else {
                                float v = outL[i * F + lane] + bb[lane];
                                v = v > 0.0f ? v : 0.0f;
                                g_xp3[rank * F + lane] = v * val;
                            }
                        }
                    } else if (lane == 0) {
                        g_pos[i] = -1;
                    }
                }
            }
        }
        gsync();

        // Phase E: remap + compact edges -> layer l+1 + degree count
        if (l < 3) {
            int iters = (El + NT - 1) / NT;
            for (int it = 0; it < iters; it++) {
                int e = it * NT + gtid;
                bool valid = false; int nr = 0, nc = 0;
                if (e < El) {
                    nr = g_pos[g_row[l][e]];
                    nc = g_pos[g_col[l][e]];
                    valid = (nr >= 0) && (nc >= 0);
                }
                unsigned int m = __ballot_sync(0xFFFFFFFFu, valid);
                if (m) {
                    int leader = __ffs(m) - 1;
                    int base = 0;
                    if (lane == leader) base = atomicAdd(&g_ecnt[l + 1], __popc(m));
                    base = __shfl_sync(0xFFFFFFFFu, base, leader);
                    if (valid) {
                        int ppos = base + __popc(m & ((1u << lane) - 1u));
                        g_row[l + 1][ppos] = nr;
                        g_col[l + 1][ppos] = nc;
                        atomicAdd(&g_deg[l + 1][nc], 1.0f);
                    }
                }
            }
            gsync();
        }
    }

    // ---------- FC head (split-K matvecs, bias pre-seeded) ----------
    {   // fc1: 1408 -> 1024, 64 chunks of 22
        int j = gtid & 1023, ch = gtid >> 10;
        int i0 = ch * 22;
        float acc = 0.0f;
        #pragma unroll
        for (int i = 0; i < 22; i++) acc += g_xp3[i0 + i] * fw1[(i0 + i) * 1024 + j];
        atomicAdd(&g_h1[j], acc);
    }
    gsync();
    {   // fc2: 1024 -> 512, 128 chunks of 8
        int j = gtid & 511, ch = gtid >> 9;
        int i0 = ch * 8;
        float acc = 0.0f;
        #pragma unroll
        for (int i = 0; i < 8; i++) acc += g_h1[i0 + i] * fw2[(i0 + i) * 512 + j];
        atomicAdd(&g_h2[j], acc);
    }
    gsync();
    if (gtid < 96 * 64) {  // fc3: 512 -> 96, 64 chunks of 8
        int j = gtid % 96, ch = gtid / 96;
        int i0 = ch * 8;
        float acc = 0.0f;
        #pragma unroll
        for (int i = 0; i < 8; i++) acc += g_h2[i0 + i] * fw3[(i0 + i) * 96 + j];
        atomicAdd(&out[j], acc);
    }
}

extern "C" void kernel_launch(void* const* d_in, const int* in_sizes, int n_in,
                              void* d_out, int out_size) {
    gcn_fused<<<GRID, BLOCK>>>(
        (const float*)d_in[0],  (const int*)d_in[1],
        (const float*)d_in[3],  (const float*)d_in[4],
        (const float*)d_in[5],  (const float*)d_in[6],
        (const float*)d_in[7],  (const float*)d_in[8],
        (const float*)d_in[9],  (const float*)d_in[10],
        (const float*)d_in[11], (const float*)d_in[12],
        (const float*)d_in[13], (const float*)d_in[14],
        (const float*)d_in[15], (const float*)d_in[16],
        (const float*)d_in[17], (const float*)d_in[18],
        (const float*)d_in[19], (const float*)d_in[20],
        (float*)d_out);
}